// round 17
// baseline (speedup 1.0000x reference)
#include <cuda_runtime.h>
#include <cuda_fp16.h>
#include <math_constants.h>
#include <cstdint>

#define D_MODEL   2048
#define NUM_HEADS 16
#define SEQ_LEN   2048
#define BATCH     2
#define D_HEAD    128
#define MROWS     (BATCH * SEQ_LEN)     // 4096
#define NQKV      (3 * D_MODEL)

// ---------------------------------------------------------------------------
// Scratch
// ---------------------------------------------------------------------------
__device__ __half g_A[(size_t)MROWS * D_MODEL];         // x / ctx, fp16
__device__ __half g_Wqkv[(size_t)NQKV * D_MODEL];       // Wq|Wk|Wv transposed [n][k]
__device__ __half g_Wo[(size_t)D_MODEL * D_MODEL];      // W_out transposed [n][k]
#define HSZ ((size_t)BATCH * NUM_HEADS * SEQ_LEN * D_HEAD)
__device__ __half g_Qh[HSZ];
__device__ __half g_Kh[HSZ];
__device__ __half g_Vh[HSZ];

__device__ __forceinline__ uint32_t smem_to_u32(const void* p) {
    uint32_t a;
    asm("{ .reg .u64 t; cvta.to.shared.u64 t, %1; cvt.u32.u64 %0, t; }" : "=r"(a) : "l"(p));
    return a;
}
__device__ __forceinline__ void mma16816(
    float* c, const uint32_t* a, const uint32_t* b)
{
    asm volatile(
        "mma.sync.aligned.m16n8k16.row.col.f32.f16.f16.f32 "
        "{%0,%1,%2,%3}, {%4,%5,%6,%7}, {%8,%9}, {%0,%1,%2,%3};"
        : "+f"(c[0]), "+f"(c[1]), "+f"(c[2]), "+f"(c[3])
        : "r"(a[0]), "r"(a[1]), "r"(a[2]), "r"(a[3]), "r"(b[0]), "r"(b[1]));
}
__device__ __forceinline__ void ldsm_x4(uint32_t* r, uint32_t addr)
{
    asm volatile("ldmatrix.sync.aligned.m8n8.x4.shared.b16 {%0,%1,%2,%3}, [%4];"
                 : "=r"(r[0]), "=r"(r[1]), "=r"(r[2]), "=r"(r[3]) : "r"(addr));
}
__device__ __forceinline__ void ldsm_x4_t(uint32_t* r, uint32_t addr)
{
    asm volatile("ldmatrix.sync.aligned.m8n8.x4.trans.shared.b16 {%0,%1,%2,%3}, [%4];"
                 : "=r"(r[0]), "=r"(r[1]), "=r"(r[2]), "=r"(r[3]) : "r"(addr));
}
__device__ __forceinline__ void cp_async16(uint32_t dst, const void* src)
{
    asm volatile("cp.async.cg.shared.global [%0], [%1], 16;" :: "r"(dst), "l"(src));
}
// 256-byte-row swizzle (16 chunks of 16B; bit3 passthrough, low3 XOR row)
__device__ __forceinline__ uint32_t swz(int r, int c)
{
    return (uint32_t)(r * 256 + (((c & 8) | ((c & 7) ^ (r & 7))) << 4));
}

// ---------------------------------------------------------------------------
// Conversions
// ---------------------------------------------------------------------------
__global__ __launch_bounds__(256) void conv_act(
    const float* __restrict__ src, __half* __restrict__ dst)
{
    int t = blockIdx.x * blockDim.x + threadIdx.x;
    float4 v = *(const float4*)(src + (size_t)t * 4);
    __half2 a = __floats2half2_rn(v.x, v.y);
    __half2 b = __floats2half2_rn(v.z, v.w);
    *(uint32_t*)(dst + (size_t)t * 4)     = *(uint32_t*)&a;
    *(uint32_t*)(dst + (size_t)t * 4 + 2) = *(uint32_t*)&b;
}

__global__ __launch_bounds__(256) void conv_wt_all(
    const float* __restrict__ Wq, const float* __restrict__ Wk,
    const float* __restrict__ Wv, const float* __restrict__ Wo,
    __half* __restrict__ Wqkv, __half* __restrict__ Wout)
{
    __shared__ float tile[32][33];
    const int z = blockIdx.z;
    const float* W = (z == 0) ? Wq : (z == 1) ? Wk : (z == 2) ? Wv : Wo;
    __half* dst = (z < 3) ? (Wqkv + (size_t)z * D_MODEL * D_MODEL) : Wout;

    int tx = threadIdx.x & 31, ty = threadIdx.x >> 5;
    int n0 = blockIdx.x * 32, k0 = blockIdx.y * 32;
#pragma unroll
    for (int j = 0; j < 4; j++)
        tile[ty + 8*j][tx] = W[(size_t)(k0 + ty + 8*j) * D_MODEL + n0 + tx];
    __syncthreads();
#pragma unroll
    for (int j = 0; j < 4; j++) {
        int n = n0 + ty + 8*j;
        dst[(size_t)n * D_MODEL + k0 + tx] = __float2half_rn(tile[tx][ty + 8*j]);
    }
}

// ---------------------------------------------------------------------------
// Pipelined mma.sync fp16 GEMM core. K=2048, BK=128.
// CTA 128x128, 4 warps 64x64, 3-stage cp.async, 256B-row swizzled smem.
// ---------------------------------------------------------------------------
#define BKg 128
#define NCH1 (D_MODEL / BKg)            // 16
#define STAGE_BYTES 65536               // A 32KB + B 32KB
#define GEMM_SMEM (3 * STAGE_BYTES)     // 196608

struct GemmAcc { float a[4][8][4]; };

__device__ __forceinline__ void gemm_mainloop(
    const __half* __restrict__ A, const __half* __restrict__ B,
    int row0, int col0, GemmAcc& acc)
{
    extern __shared__ char gsm[];
    const uint32_t smem_base = smem_to_u32(gsm);
    const int tid  = threadIdx.x;
    const int wid  = tid >> 5;
    const int lane = tid & 31;
    const int warp_m = (wid & 1) * 64;
    const int warp_n = (wid >> 1) * 64;

#pragma unroll
    for (int mt = 0; mt < 4; mt++)
#pragma unroll
        for (int nt = 0; nt < 8; nt++)
#pragma unroll
            for (int i = 0; i < 4; i++) acc.a[mt][nt][i] = 0.0f;

    const __half* Abase = A + (size_t)row0 * D_MODEL;
    const __half* Bbase = B + (size_t)col0 * D_MODEL;

    auto issue_stage = [&](int kc, int s) {
        const uint32_t stA = smem_base + s * STAGE_BYTES;
        const uint32_t stB = stA + 32768;
        const __half* gA = Abase + (size_t)kc * BKg;
        const __half* gB = Bbase + (size_t)kc * BKg;
#pragma unroll
        for (int i = 0; i < 16; i++) {
            int id = tid + i * 128;
            int r = id >> 4, c = id & 15;
            uint32_t soff = swz(r, c);
            cp_async16(stA + soff, gA + (size_t)r * D_MODEL + c * 8);
            cp_async16(stB + soff, gB + (size_t)r * D_MODEL + c * 8);
        }
        asm volatile("cp.async.commit_group;" ::: "memory");
    };

    issue_stage(0, 0);
    issue_stage(1, 1);

    const int l16   = lane & 15;
    const int aCsel = lane >> 4;
    const int bRow  = (lane & 7) + ((lane & 16) >> 1);
    const int bCsel = (lane >> 3) & 1;

    for (int kc = 0; kc < NCH1; kc++) {
        if (kc + 2 < NCH1) { asm volatile("cp.async.wait_group 1;" ::: "memory"); }
        else               { asm volatile("cp.async.wait_group 0;" ::: "memory"); }
        __syncthreads();
        if (kc + 2 < NCH1) issue_stage(kc + 2, (kc + 2) % 3);

        const int s = kc % 3;
        const uint32_t stA = smem_base + s * STAGE_BYTES;
        const uint32_t stB = stA + 32768;

#pragma unroll
        for (int ks = 0; ks < 8; ks++) {
            uint32_t afrag[4][4], bfrag[8][2];
#pragma unroll
            for (int mt = 0; mt < 4; mt++) {
                int r = warp_m + mt * 16 + l16;
                ldsm_x4(afrag[mt], stA + swz(r, 2 * ks + aCsel));
            }
#pragma unroll
            for (int ntp = 0; ntp < 4; ntp++) {
                int n = warp_n + ntp * 16 + bRow;
                uint32_t q[4];
                ldsm_x4(q, stB + swz(n, 2 * ks + bCsel));
                bfrag[2*ntp][0] = q[0]; bfrag[2*ntp][1] = q[1];
                bfrag[2*ntp+1][0] = q[2]; bfrag[2*ntp+1][1] = q[3];
            }
#pragma unroll
            for (int mt = 0; mt < 4; mt++)
#pragma unroll
                for (int nt = 0; nt < 8; nt++)
                    mma16816(acc.a[mt][nt], afrag[mt], bfrag[nt]);
        }
    }
}

// Fused QKV projection. Q (scaled), K, V -> fp16 per-head layout.
__global__ __launch_bounds__(128) void gemm_qkv(
    const __half* __restrict__ A, const __half* __restrict__ Wqkv,
    __half* __restrict__ Qh, __half* __restrict__ Kh, __half* __restrict__ Vh)
{
    const int row0 = blockIdx.y * 128;
    const int col0 = blockIdx.x * 128;
    GemmAcc acc;
    gemm_mainloop(A, Wqkv, row0, col0, acc);

    const int wid  = threadIdx.x >> 5;
    const int lane = threadIdx.x & 31;
    const int warp_m = (wid & 1) * 64;
    const int warp_n = (wid >> 1) * 64;
    const int lr  = lane >> 2;
    const int lc2 = (lane & 3) * 2;

    const int proj = col0 >> 11;                // 0=Q 1=K 2=V
    const int hh   = (col0 & 2047) >> 7;
    __half* dst = (proj == 0) ? Qh : (proj == 1) ? Kh : Vh;
    const float scale = (proj == 0) ? 0.08838834764831845f : 1.0f;

#pragma unroll
    for (int mt = 0; mt < 4; mt++) {
        int r = row0 + warp_m + mt * 16 + lr;
        int b = r >> 11, t = r & (SEQ_LEN - 1);
        size_t base0 = ((size_t)(b * NUM_HEADS + hh) * SEQ_LEN + t) * D_HEAD;
        size_t base1 = base0 + 8 * D_HEAD;
#pragma unroll
        for (int nt = 0; nt < 8; nt++) {
            int d = warp_n + nt * 8 + lc2;
            __half2 v0 = __floats2half2_rn(acc.a[mt][nt][0] * scale, acc.a[mt][nt][1] * scale);
            __half2 v1 = __floats2half2_rn(acc.a[mt][nt][2] * scale, acc.a[mt][nt][3] * scale);
            *(uint32_t*)(dst + base0 + d) = *(uint32_t*)&v0;
            *(uint32_t*)(dst + base1 + d) = *(uint32_t*)&v1;
        }
    }
}

// Output projection -> fp32 d_out.
__global__ __launch_bounds__(128) void gemm_out(
    const __half* __restrict__ A, const __half* __restrict__ B,
    float* __restrict__ C)
{
    const int row0 = blockIdx.y * 128;
    const int col0 = blockIdx.x * 128;
    GemmAcc acc;
    gemm_mainloop(A, B, row0, col0, acc);

    const int wid  = threadIdx.x >> 5;
    const int lane = threadIdx.x & 31;
    const int warp_m = (wid & 1) * 64;
    const int warp_n = (wid >> 1) * 64;
    const int lr  = lane >> 2;
    const int lc2 = (lane & 3) * 2;
#pragma unroll
    for (int mt = 0; mt < 4; mt++) {
        int r = row0 + warp_m + mt * 16 + lr;
#pragma unroll
        for (int nt = 0; nt < 8; nt++) {
            int c = col0 + warp_n + nt * 8 + lc2;
            *(float2*)(C + (size_t)r * D_MODEL + c)       = make_float2(acc.a[mt][nt][0], acc.a[mt][nt][1]);
            *(float2*)(C + (size_t)(r + 8) * D_MODEL + c) = make_float2(acc.a[mt][nt][2], acc.a[mt][nt][3]);
        }
    }
}

// ---------------------------------------------------------------------------
// Tensor-core causal flash attention, pure fp16, BN=128 KV blocks.
// smem: Q 32K | 2 stages x (K 32K + V 32K) = 160KB total.
// ---------------------------------------------------------------------------
#define BMa 128
#define BNa 128
#define KV_STAGE 65536
#define ATT_SMEM (32768 + 2 * KV_STAGE)   // 163840

__global__ __launch_bounds__(256, 1) void attn_mma(
    const __half* __restrict__ Qh, const __half* __restrict__ Kh,
    const __half* __restrict__ Vh, __half* __restrict__ CTX)
{
    extern __shared__ char smemraw[];
    const uint32_t sb = smem_to_u32(smemraw);
    const int tid = threadIdx.x, wid = tid >> 5, lane = tid & 31;
    const int h  = blockIdx.x;
    const int qb = gridDim.y - 1 - blockIdx.y;   // heavy blocks first
    const int b  = blockIdx.z;
    const int warp_m = wid * 16;

    const size_t head_off = (size_t)(b * NUM_HEADS + h) * SEQ_LEN * D_HEAD;
    const uint32_t sQ = sb;

    {
        const __half* qg = Qh + head_off + (size_t)qb * BMa * D_HEAD;
#pragma unroll
        for (int i = 0; i < 8; i++) {
            int id = tid + i * 256;
            int r = id >> 4, c = id & 15;
            cp_async16(sQ + swz(r, c), qg + r * 128 + c * 8);
        }
        asm volatile("cp.async.commit_group;" ::: "memory");
    }

    const int nkb = qb + 1;
    auto issue_kv = [&](int kb, int s) {
        uint32_t st = sb + 32768 + s * KV_STAGE;
        const __half* kh = Kh + head_off + (size_t)kb * BNa * D_HEAD;
        const __half* vh = Vh + head_off + (size_t)kb * BNa * D_HEAD;
#pragma unroll
        for (int i = 0; i < 8; i++) {
            int id = tid + i * 256;
            int r = id >> 4, c = id & 15;
            uint32_t so = swz(r, c);
            int go = r * 128 + c * 8;
            cp_async16(st +         so, kh + go);
            cp_async16(st + 32768 + so, vh + go);
        }
        asm volatile("cp.async.commit_group;" ::: "memory");
    };
    issue_kv(0, 0);

    float oacc[16][4];
#pragma unroll
    for (int j = 0; j < 16; j++)
#pragma unroll
        for (int i = 0; i < 4; i++) oacc[j][i] = 0.0f;
    float m0 = -1e30f, m1 = -1e30f, l0 = 0.0f, l1 = 0.0f;
    const int lr = lane >> 2, lc2 = (lane & 3) * 2;

    for (int kb = 0; kb < nkb; kb++) {
        asm volatile("cp.async.wait_group 0;" ::: "memory");
        __syncthreads();
        if (kb + 1 < nkb) issue_kv(kb + 1, (kb + 1) & 1);

        const uint32_t st = sb + 32768 + (kb & 1) * KV_STAGE;
        float sacc[16][4];
#pragma unroll
        for (int j = 0; j < 16; j++)
#pragma unroll
            for (int i = 0; i < 4; i++) sacc[j][i] = 0.0f;

        // score: S = Qh · Kh^T  (128 queries x 128 keys)
#pragma unroll
        for (int ks = 0; ks < 8; ks++) {
            uint32_t a[4];
            {
                int r = warp_m + (lane & 15);
                ldsm_x4(a, sQ + swz(r, 2 * ks + (lane >> 4)));
            }
            uint32_t bf[16][2];
#pragma unroll
            for (int g4 = 0; g4 < 8; g4++) {
                int n = g4 * 16 + (lane & 7) + ((lane & 16) >> 1);
                uint32_t q[4];
                ldsm_x4(q, st + swz(n, 2 * ks + ((lane >> 3) & 1)));
                bf[2*g4][0] = q[0]; bf[2*g4][1] = q[1];
                bf[2*g4+1][0] = q[2]; bf[2*g4+1][1] = q[3];
            }
#pragma unroll
            for (int j = 0; j < 16; j++) mma16816(sacc[j], a, bf[j]);
        }

        if (kb == qb) {   // diagonal block: col > row masked
            const int ra = warp_m + lr, rb = ra + 8;
#pragma unroll
            for (int j = 0; j < 16; j++) {
                int colb = 8 * j + lc2;
                if (colb     > ra) sacc[j][0] = -1e30f;
                if (colb + 1 > ra) sacc[j][1] = -1e30f;
                if (colb     > rb) sacc[j][2] = -1e30f;
                if (colb + 1 > rb) sacc[j][3] = -1e30f;
            }
        }

        float rmx0 = -1e30f, rmx1 = -1e30f;
#pragma unroll
        for (int j = 0; j < 16; j++) {
            rmx0 = fmaxf(rmx0, fmaxf(sacc[j][0], sacc[j][1]));
            rmx1 = fmaxf(rmx1, fmaxf(sacc[j][2], sacc[j][3]));
        }
        rmx0 = fmaxf(rmx0, __shfl_xor_sync(0xffffffffu, rmx0, 1));
        rmx0 = fmaxf(rmx0, __shfl_xor_sync(0xffffffffu, rmx0, 2));
        rmx1 = fmaxf(rmx1, __shfl_xor_sync(0xffffffffu, rmx1, 1));
        rmx1 = fmaxf(rmx1, __shfl_xor_sync(0xffffffffu, rmx1, 2));
        float mn0 = fmaxf(m0, rmx0), mn1 = fmaxf(m1, rmx1);
        float c0 = __expf(m0 - mn0), c1 = __expf(m1 - mn1);
        m0 = mn0; m1 = mn1;
        float ps0 = 0.0f, ps1 = 0.0f;
#pragma unroll
        for (int j = 0; j < 16; j++) {
            sacc[j][0] = __expf(sacc[j][0] - mn0); ps0 += sacc[j][0];
            sacc[j][1] = __expf(sacc[j][1] - mn0); ps0 += sacc[j][1];
            sacc[j][2] = __expf(sacc[j][2] - mn1); ps1 += sacc[j][2];
            sacc[j][3] = __expf(sacc[j][3] - mn1); ps1 += sacc[j][3];
        }
        l0 = l0 * c0 + ps0;
        l1 = l1 * c1 + ps1;
#pragma unroll
        for (int j = 0; j < 16; j++) {
            oacc[j][0] *= c0; oacc[j][1] *= c0;
            oacc[j][2] *= c1; oacc[j][3] *= c1;
        }

        // PV: O += P · V  (P: 128x128 fp16, V: 128x128)
        const uint32_t sV = st + 32768;
#pragma unroll
        for (int s = 0; s < 8; s++) {
            uint32_t pfrag[4];
            {
                __half2 p0 = __floats2half2_rn(sacc[2*s][0],   sacc[2*s][1]);
                __half2 p1 = __floats2half2_rn(sacc[2*s][2],   sacc[2*s][3]);
                __half2 p2 = __floats2half2_rn(sacc[2*s+1][0], sacc[2*s+1][1]);
                __half2 p3 = __floats2half2_rn(sacc[2*s+1][2], sacc[2*s+1][3]);
                pfrag[0] = *(uint32_t*)&p0; pfrag[1] = *(uint32_t*)&p1;
                pfrag[2] = *(uint32_t*)&p2; pfrag[3] = *(uint32_t*)&p3;
            }
            uint32_t bv[16][2];
            const int mid = lane >> 3;
#pragma unroll
            for (int g = 0; g < 8; g++) {
                int r = s * 16 + 8 * (mid & 1) + (lane & 7);
                uint32_t q[4];
                ldsm_x4_t(q, sV + swz(r, 2 * g + (mid >> 1)));
                bv[2*g][0] = q[0]; bv[2*g][1] = q[1];
                bv[2*g+1][0] = q[2]; bv[2*g+1][1] = q[3];
            }
#pragma unroll
            for (int j = 0; j < 16; j++) mma16816(oacc[j], pfrag, bv[j]);
        }
    }

    l0 += __shfl_xor_sync(0xffffffffu, l0, 1);
    l0 += __shfl_xor_sync(0xffffffffu, l0, 2);
    l1 += __shfl_xor_sync(0xffffffffu, l1, 1);
    l1 += __shfl_xor_sync(0xffffffffu, l1, 2);
    const float il0 = 1.0f / l0, il1 = 1.0f / l1;

    const int ra = qb * BMa + warp_m + lr;
    size_t base0 = ((size_t)(b * SEQ_LEN) + ra) * D_MODEL + h * D_HEAD;
    size_t base1 = base0 + (size_t)8 * D_MODEL;
#pragma unroll
    for (int j = 0; j < 16; j++) {
        int d = 8 * j + lc2;
        __half2 v0 = __floats2half2_rn(oacc[j][0] * il0, oacc[j][1] * il0);
        __half2 v1 = __floats2half2_rn(oacc[j][2] * il1, oacc[j][3] * il1);
        *(uint32_t*)(CTX + base0 + d) = *(uint32_t*)&v0;
        *(uint32_t*)(CTX + base1 + d) = *(uint32_t*)&v1;
    }
}

// ---------------------------------------------------------------------------
// Launch
// ---------------------------------------------------------------------------
extern "C" void kernel_launch(void* const* d_in, const int* in_sizes, int n_in,
                              void* d_out, int out_size)
{
    const float* x     = (const float*)d_in[0];
    const float* q_w   = (const float*)d_in[1];
    const float* k_w   = (const float*)d_in[2];
    const float* v_w   = (const float*)d_in[3];
    const float* w_out = (const float*)d_in[4];
    float* out = (float*)d_out;

    __half *A, *Wqkv, *Wo, *Qh, *Kh, *Vh;
    cudaGetSymbolAddress((void**)&A,    g_A);
    cudaGetSymbolAddress((void**)&Wqkv, g_Wqkv);
    cudaGetSymbolAddress((void**)&Wo,   g_Wo);
    cudaGetSymbolAddress((void**)&Qh,   g_Qh);
    cudaGetSymbolAddress((void**)&Kh,   g_Kh);
    cudaGetSymbolAddress((void**)&Vh,   g_Vh);

    cudaFuncSetAttribute(gemm_qkv, cudaFuncAttributeMaxDynamicSharedMemorySize, GEMM_SMEM);
    cudaFuncSetAttribute(gemm_out, cudaFuncAttributeMaxDynamicSharedMemorySize, GEMM_SMEM);
    cudaFuncSetAttribute(attn_mma, cudaFuncAttributeMaxDynamicSharedMemorySize, ATT_SMEM);

    // 1. weight transpose/convert + activation convert
    dim3 wgrid(D_MODEL / 32, D_MODEL / 32, 4);
    conv_wt_all<<<wgrid, 256>>>(q_w, k_w, v_w, w_out, Wqkv, Wo);
    conv_act<<<(MROWS * D_MODEL / 4) / 256, 256>>>(x, A);

    // 2. fused QKV projection
    dim3 qkvgrid(NQKV / 128, MROWS / 128);        // (48, 32)
    gemm_qkv<<<qkvgrid, 128, GEMM_SMEM>>>(A, Wqkv, Qh, Kh, Vh);

    // 3. pure-fp16 tensor-core causal attention -> fp16 ctx into A
    dim3 agrid(NUM_HEADS, SEQ_LEN / BMa, BATCH);  // (16,16,2), heavy qb first
    attn_mma<<<agrid, 256, ATT_SMEM>>>(Qh, Kh, Vh, A);

    // 4. output projection
    dim3 ogrid(D_MODEL / 128, MROWS / 128);       // (16, 32)
    gemm_out<<<ogrid, 128, GEMM_SMEM>>>(A, Wo, out);
}